// round 11
// baseline (speedup 1.0000x reference)
#include <cuda_runtime.h>
#include <math.h>

#define DIMX   20
#define DD     21
#define NPT    2048
#define MCc    32
#define UNITS  128
#define TP     16
#define BTOT   69632
#define NTILES (BTOT / TP)
#define THREADS 512

#define SIGc   0.2f
#define MUc    0.05f
#define Rc     0.05f
#define DELTAc 0.01f

__device__ float g_L[DIMX * DIMX];
__device__ float g_WT[4 * UNITS * UNITS];   // [mat][a][b] = W[b][a]
__device__ float g_UcatT[5 * UNITS * 24];   // [v][j][24] padded
__device__ float g_X[BTOT * DD];
__device__ float g_FP[BTOT * DD];
__device__ float g_FVAL[BTOT];

// smem (floats): matmul operands only; activations live in registers.
#define SM_X    0                    // 336
#define SM_S0   336                  // 2048
#define SM_S1   (SM_S0 + 2048)
#define SM_SR   (SM_S1 + 2048)
#define SM_T0   (SM_SR + 2048)       // staging daz / Daz
#define SM_T1   (SM_T0 + 2048)       // dag / Dag
#define SM_T2   (SM_T1 + 2048)       // dar / Dar
#define SM_T3   (SM_T2 + 2048)       // dah / Dah
#define SM_FRED (SM_T3 + 2048)       // 64
#define SM_TOT  (SM_FRED + 64)       // 14736 floats = 58944 B -> L1D ~169 KB

typedef unsigned long long u64t;

__device__ __forceinline__ u64t pack2(float lo, float hi) {
    u64t r;
    asm("mov.b64 %0, {%1, %2};" : "=l"(r) : "f"(lo), "f"(hi));
    return r;
}
__device__ __forceinline__ float2 unpack2(u64t v) {
    float2 f;
    asm("mov.b64 {%0, %1}, %2;" : "=f"(f.x), "=f"(f.y) : "l"(v));
    return f;
}
__device__ __forceinline__ u64t ffma2(u64t a, u64t b, u64t c) {
    u64t d;
    asm("fma.rn.f32x2 %0, %1, %2, %3;" : "=l"(d) : "l"(a), "l"(b), "l"(c));
    return d;
}
__device__ __forceinline__ float ftanh(float x) {
    float ax = fabsf(x);
    float t = __expf(-2.0f * ax);
    float r = __fdividef(1.0f - t, 1.0f + t);
    return copysignf(r, x);
}

__global__ void prep_kernel(const float* __restrict__ wz, const float* __restrict__ wg,
                            const float* __restrict__ wr, const float* __restrict__ wh,
                            const float* __restrict__ uz, const float* __restrict__ ug,
                            const float* __restrict__ ur, const float* __restrict__ uh,
                            const float* __restrict__ w1)
{
    int idx = blockIdx.x * blockDim.x + threadIdx.x;
    int stride = gridDim.x * blockDim.x;

    for (int t = idx; t < 4 * UNITS * UNITS; t += stride) {
        int mat = t >> 14;
        int r   = t & 16383;
        int a   = r >> 7;
        int b   = r & 127;
        const float* W = (mat == 0) ? wz : (mat == 1) ? wg : (mat == 2) ? wr : wh;
        g_WT[t] = W[b * UNITS + a];
    }
    for (int t = idx; t < 5 * UNITS * 24; t += stride) {
        int v = t / (UNITS * 24);
        int r = t % (UNITS * 24);
        int j = r / 24;
        int d = r % 24;
        const float* U = (v == 0) ? uz : (v == 1) ? ug : (v == 2) ? ur : (v == 3) ? uh : w1;
        g_UcatT[t] = (d < DD) ? U[d * UNITS + j] : 0.0f;
    }
    if (idx == 0) {
        double Ld[DIMX][DIMX];
        for (int i = 0; i < DIMX; i++) {
            for (int j2 = 0; j2 <= i; j2++) {
                double s = 0.01 * (0.5 + (i == j2 ? 0.5 : 0.0));
                for (int k = 0; k < j2; k++) s -= Ld[i][k] * Ld[j2][k];
                Ld[i][j2] = (i == j2) ? sqrt(s) : s / Ld[j2][j2];
            }
        }
        for (int i = 0; i < DIMX; i++)
            for (int j2 = 0; j2 < DIMX; j2++)
                g_L[i * DIMX + j2] = (j2 <= i) ? (float)Ld[i][j2] : 0.0f;
    }
}

__global__ void build_kernel(const float* __restrict__ inputs, const float* __restrict__ eps)
{
    int r = blockIdx.x * blockDim.x + threadIdx.x;
    if (r >= BTOT) return;
    if (r < 4096) {
        #pragma unroll
        for (int d = 0; d < DD; d++) g_X[r * DD + d] = inputs[r * DD + d];
    } else {
        int q = r - 4096;
        int m = q >> 11;
        int n = q & 2047;
        float xr[DD];
        #pragma unroll
        for (int d = 0; d < DD; d++) xr[d] = inputs[n * DD + d];
        float e[DIMX];
        #pragma unroll
        for (int d = 0; d < DIMX; d++) e[d] = eps[(m * NPT + n) * DIMX + d];
        #pragma unroll
        for (int k = 0; k < DIMX; k++) {
            float acc = 0.f;
            #pragma unroll
            for (int d = 0; d < DIMX; d++) acc += e[d] * g_L[k * DIMX + d];
            float sample = xr[k] + acc;
            float viol = sample * (SIGc * xr[k]);
            g_X[r * DD + k] = xr[k] + viol;
        }
        g_X[r * DD + DIMX] = xr[DIMX];
    }
}

// ---- helpers ----
__device__ __forceinline__ void st4(float* dst, const float a[4], int j, int p0) {
    *(float4*)&dst[j * TP + p0] = make_float4(a[0], a[1], a[2], a[3]);
}
// single-matrix pass: a0/a1 += S_pairs * {w,w}   (5 issues per k)
__device__ __forceinline__ void mm1(u64t& a0, u64t& a1, const float* __restrict__ W,
                                    const float* S, int j, int p0) {
    #pragma unroll 8
    for (int k = 0; k < UNITS; k++) {
        float wv = W[k * UNITS + j];
        u64t wp = pack2(wv, wv);
        ulonglong2 s = *(const ulonglong2*)&S[k * TP + p0];
        a0 = ffma2(s.x, wp, a0);
        a1 = ffma2(s.y, wp, a1);
    }
}
// x@U (21 iterations, scalar)
__device__ __forceinline__ void mmX(float acc[4], const float* __restrict__ U,
                                    const float* X, int j, int p0) {
    #pragma unroll
    for (int d = 0; d < DD; d++) {
        float wv = U[d * UNITS + j];
        float4 s = *(const float4*)&X[d * TP + p0];
        acc[0] += s.x * wv; acc[1] += s.y * wv; acc[2] += s.z * wv; acc[3] += s.w * wv;
    }
}
__device__ __forceinline__ void tanh4(float out[4], u64t a0, u64t a1) {
    float2 t0 = unpack2(a0), t1 = unpack2(a1);
    out[0] = ftanh(t0.x); out[1] = ftanh(t0.y); out[2] = ftanh(t1.x); out[3] = ftanh(t1.y);
}

__global__ __launch_bounds__(THREADS, 1)
void dgm_main(const float* __restrict__ w1, const float* __restrict__ b1,
              const float* __restrict__ uz, const float* __restrict__ wz, const float* __restrict__ bz,
              const float* __restrict__ ug, const float* __restrict__ wg, const float* __restrict__ bg,
              const float* __restrict__ ur, const float* __restrict__ wr, const float* __restrict__ br,
              const float* __restrict__ uh, const float* __restrict__ wh, const float* __restrict__ bh,
              const float* __restrict__ wout, const float* __restrict__ bout)
{
    extern __shared__ float sm[];
    const int tid = threadIdx.x;
    const int j   = tid & 127;
    const int pg  = tid >> 7;
    const int p0  = pg * 4;
    const int base = blockIdx.x * TP;
    const bool doGrad = !(blockIdx.x >= 128 && blockIdx.x < 256);

    for (int t = tid; t < TP * DD; t += THREADS) {
        int p = t / DD, d = t % DD;
        sm[SM_X + d * TP + p] = g_X[(base + p) * DD + d];
    }
    __syncthreads();

    // ---- prologue: x@U + b (kept as f32x2 pairs across the layers) ----
    u64t xzr[2], xgr[2], xrr[2], xhr[2];
    float s_cur[4];
    float slr[3][4];                     // s input of each layer (registers)
    {
        float acc[4];
        float bb;
        bb = bz[j];
        acc[0]=acc[1]=acc[2]=acc[3]=bb; mmX(acc, uz, &sm[SM_X], j, p0);
        xzr[0] = pack2(acc[0], acc[1]); xzr[1] = pack2(acc[2], acc[3]);
        bb = bg[j];
        acc[0]=acc[1]=acc[2]=acc[3]=bb; mmX(acc, ug, &sm[SM_X], j, p0);
        xgr[0] = pack2(acc[0], acc[1]); xgr[1] = pack2(acc[2], acc[3]);
        bb = br[j];
        acc[0]=acc[1]=acc[2]=acc[3]=bb; mmX(acc, ur, &sm[SM_X], j, p0);
        xrr[0] = pack2(acc[0], acc[1]); xrr[1] = pack2(acc[2], acc[3]);
        bb = bh[j];
        acc[0]=acc[1]=acc[2]=acc[3]=bb; mmX(acc, uh, &sm[SM_X], j, p0);
        xhr[0] = pack2(acc[0], acc[1]); xhr[1] = pack2(acc[2], acc[3]);
        bb = b1[j];
        acc[0]=acc[1]=acc[2]=acc[3]=bb; mmX(acc, w1, &sm[SM_X], j, p0);
        #pragma unroll
        for (int p = 0; p < 4; p++) s_cur[p] = ftanh(acc[p]);
        st4(&sm[SM_S0], s_cur, j, p0);
    }
    __syncthreads();

    // ---- forward: activations retained in registers for backward ----
    float zr[3][4], gr[3][4], rr[3][4], hr[3][4];
    #pragma unroll 1
    for (int l = 0; l < 3; l++) {
        float* Sin = (l & 1) ? &sm[SM_S1] : &sm[SM_S0];
        float* Sout = (l & 1) ? &sm[SM_S0] : &sm[SM_S1];
        #pragma unroll
        for (int p = 0; p < 4; p++) slr[l][p] = s_cur[p];

        // z / g / r: three single-matrix passes (each 64 KB, L1-resident)
        u64t a0, a1;
        a0 = xzr[0]; a1 = xzr[1];
        mm1(a0, a1, wz, Sin, j, p0);
        tanh4(zr[l], a0, a1);
        a0 = xgr[0]; a1 = xgr[1];
        mm1(a0, a1, wg, Sin, j, p0);
        tanh4(gr[l], a0, a1);
        a0 = xrr[0]; a1 = xrr[1];
        mm1(a0, a1, wr, Sin, j, p0);
        tanh4(rr[l], a0, a1);

        float sr4[4];
        #pragma unroll
        for (int p = 0; p < 4; p++) sr4[p] = s_cur[p] * rr[l][p];
        st4(&sm[SM_SR], sr4, j, p0);
        __syncthreads();

        a0 = xhr[0]; a1 = xhr[1];
        mm1(a0, a1, wh, &sm[SM_SR], j, p0);
        tanh4(hr[l], a0, a1);

        #pragma unroll
        for (int p = 0; p < 4; p++)
            s_cur[p] = (1.0f - gr[l][p]) * hr[l][p] + zr[l][p] * s_cur[p];
        if (l < 2) st4(Sout, s_cur, j, p0);
        __syncthreads();
    }

    // ---- value f = s3@w + b ----
    {
        float wv = wout[j];
        int warpId = tid >> 5;
        #pragma unroll
        for (int p = 0; p < 4; p++) {
            float v = wv * s_cur[p];
            #pragma unroll
            for (int off = 16; off; off >>= 1) v += __shfl_xor_sync(0xffffffffu, v, off);
            if ((tid & 31) == 0) sm[SM_FRED + warpId * 4 + p] = v;
        }
        __syncthreads();
        if (tid < TP) {
            int p = tid;
            int pgp = p >> 2;
            float f = bout[0];
            #pragma unroll
            for (int q = 0; q < 4; q++) f += sm[SM_FRED + (pgp * 4 + q) * 4 + (p & 3)];
            g_FVAL[base + p] = f;
        }
    }

    if (!doGrad) return;

    // ---- backward ----
    float ds[4], Daz[4], Dag[4], Dar[4], Dah[4];
    {
        float wv = wout[j];
        #pragma unroll
        for (int p = 0; p < 4; p++) {
            ds[p] = wv;
            Daz[p] = 0.f; Dag[p] = 0.f; Dar[p] = 0.f; Dah[p] = 0.f;
        }
    }

    #pragma unroll 1
    for (int l = 2; l >= 0; l--) {
        // stage A: elementwise from registers; stage daz/dag/dah to smem
        {
            float daz[4], dag[4], dah[4];
            #pragma unroll
            for (int p = 0; p < 4; p++) {
                float z = zr[l][p], g = gr[l][p], h = hr[l][p], sl = slr[l][p];
                float dsp = ds[p];
                float dh = dsp * (1.0f - g);
                float dg = -dsp * h;
                float dz = dsp * sl;
                daz[p] = dz * (1.0f - z * z);
                dag[p] = dg * (1.0f - g * g);
                dah[p] = dh * (1.0f - h * h);
                Daz[p] += daz[p]; Dag[p] += dag[p]; Dah[p] += dah[p];
                ds[p] = dsp * z;
            }
            st4(&sm[SM_T0], daz, j, p0);
            st4(&sm[SM_T1], dag, j, p0);
            st4(&sm[SM_T3], dah, j, p0);
        }
        __syncthreads();

        // stage B: dsr = dah @ Wh^T (single-matrix pass)
        float dsr[4];
        {
            u64t b0 = pack2(0.f, 0.f), b1p = pack2(0.f, 0.f);
            mm1(b0, b1p, g_WT + 3 * UNITS * UNITS, &sm[SM_T3], j, p0);
            float2 t0 = unpack2(b0), t1 = unpack2(b1p);
            dsr[0] = t0.x; dsr[1] = t0.y; dsr[2] = t1.x; dsr[3] = t1.y;
        }

        // stage C: dar from registers; stage to smem
        {
            float dar[4];
            #pragma unroll
            for (int p = 0; p < 4; p++) {
                float r = rr[l][p], sl = slr[l][p];
                ds[p] += dsr[p] * r;
                dar[p] = (dsr[p] * sl) * (1.0f - r * r);
                Dar[p] += dar[p];
            }
            st4(&sm[SM_T2], dar, j, p0);
        }
        __syncthreads();

        // stage D: three single-matrix passes
        {
            u64t d0 = pack2(ds[0], ds[1]), d1 = pack2(ds[2], ds[3]);
            mm1(d0, d1, g_WT + 0 * UNITS * UNITS, &sm[SM_T0], j, p0);
            mm1(d0, d1, g_WT + 1 * UNITS * UNITS, &sm[SM_T1], j, p0);
            mm1(d0, d1, g_WT + 2 * UNITS * UNITS, &sm[SM_T2], j, p0);
            float2 t0 = unpack2(d0), t1 = unpack2(d1);
            ds[0] = t0.x; ds[1] = t0.y; ds[2] = t1.x; ds[3] = t1.y;
        }
        __syncthreads();   // WAR: next stage A rewrites staging arrays
    }

    // write Σda accumulators + da1 for the dx product
    {
        float da1[4];
        #pragma unroll
        for (int p = 0; p < 4; p++) {
            float s0 = slr[0][p];
            da1[p] = ds[p] * (1.0f - s0 * s0);
        }
        st4(&sm[SM_T0], Daz, j, p0);
        st4(&sm[SM_T1], Dag, j, p0);
        st4(&sm[SM_T2], Dar, j, p0);
        st4(&sm[SM_T3], Dah, j, p0);
        st4(&sm[SM_SR], da1, j, p0);
    }
    __syncthreads();

    // dx stage 1: partials over (p, d-quad, v) -> scratch in S0 buffer
    if (tid < 480) {
        int v  = tid % 5;
        int dq = (tid / 5) % 6;
        int p  = tid / 30;
        int d0 = dq * 4;
        const float* slot =
            (v == 0) ? &sm[SM_T0] : (v == 1) ? &sm[SM_T1] :
            (v == 2) ? &sm[SM_T2] : (v == 3) ? &sm[SM_T3] : &sm[SM_SR];
        const float* Ut = g_UcatT + v * UNITS * 24;
        float acc[4] = {0.f, 0.f, 0.f, 0.f};
        #pragma unroll 8
        for (int k = 0; k < UNITS; k++) {
            float a = slot[k * TP + p];
            float4 u = *(const float4*)&Ut[k * 24 + d0];
            acc[0] += a * u.x; acc[1] += a * u.y; acc[2] += a * u.z; acc[3] += a * u.w;
        }
        *(float4*)&sm[SM_S0 + ((p * 6 + dq) * 5 + v) * 4] = make_float4(acc[0], acc[1], acc[2], acc[3]);
    }
    __syncthreads();

    // dx stage 2: combine 5 partials, coalesced-ish write
    if (tid < 96) {
        int p  = tid / 6;
        int dq = tid % 6;
        int d0 = dq * 4;
        float acc[4] = {0.f, 0.f, 0.f, 0.f};
        #pragma unroll
        for (int v = 0; v < 5; v++) {
            float4 t = *(const float4*)&sm[SM_S0 + ((p * 6 + dq) * 5 + v) * 4];
            acc[0] += t.x; acc[1] += t.y; acc[2] += t.z; acc[3] += t.w;
        }
        #pragma unroll
        for (int i = 0; i < 4; i++) {
            int d = d0 + i;
            if (d < DD) g_FP[(base + p) * DD + d] = acc[i];
        }
    }
}

__global__ void epilogue_kernel(float* __restrict__ out)
{
    int warpId = threadIdx.x >> 5;
    int lane   = threadIdx.x & 31;
    int n = blockIdx.x * 8 + warpId;
    if (n >= NPT) return;

    const float* fp1 = &g_FP[n * DD];
    const float* x1r = &g_X[n * DD];
    int rp = (4096 + lane * NPT + n) * DD;
    const float* fpp = &g_FP[rp];
    const float* xp  = &g_X[rp];

    float part = 0.f;
    #pragma unroll
    for (int k = 0; k < DIMX; k++) {
        float viol = xp[k] - x1r[k];
        part += (fpp[k] - fp1[k]) * viol;
    }
    #pragma unroll
    for (int off = 16; off; off >>= 1) part += __shfl_xor_sync(0xffffffffu, part, off);

    if (lane == 0) {
        float term12 = part / (DELTAc * (float)MCc);
        float term11 = fp1[DIMX];
        #pragma unroll
        for (int k = 0; k < DIMX; k++) term11 += MUc * x1r[k] * fp1[k];
        out[n] = term11 + 0.5f * term12 - Rc * g_FVAL[n];

        const float* x2r = &g_X[(NPT + n) * DD];
        float prod = 1.f;
        #pragma unroll
        for (int k = 0; k < DIMX; k++) prod *= x2r[k];
        float payoff = powf(prod, 1.0f / (float)DIMX);
        payoff = fmaxf(payoff, 0.f);
        out[NPT + n] = g_FVAL[NPT + n] - payoff;
    }
}

extern "C" void kernel_launch(void* const* d_in, const int* in_sizes, int n_in,
                              void* d_out, int out_size)
{
    (void)in_sizes; (void)n_in; (void)out_size;
    const float* inputs = (const float*)d_in[0];
    const float* eps    = (const float*)d_in[1];
    const float* w1  = (const float*)d_in[2];
    const float* b1  = (const float*)d_in[3];
    const float* uzl = (const float*)d_in[4];
    const float* wzl = (const float*)d_in[5];
    const float* bzl = (const float*)d_in[6];
    const float* ugl = (const float*)d_in[7];
    const float* wgl = (const float*)d_in[8];
    const float* bgl = (const float*)d_in[9];
    const float* url = (const float*)d_in[10];
    const float* wrl = (const float*)d_in[11];
    const float* brl = (const float*)d_in[12];
    const float* uhl = (const float*)d_in[13];
    const float* whl = (const float*)d_in[14];
    const float* bhl = (const float*)d_in[15];
    const float* w   = (const float*)d_in[16];
    const float* b   = (const float*)d_in[17];
    float* out = (float*)d_out;

    const int smem_bytes = SM_TOT * (int)sizeof(float);
    static bool attr_set = false;
    if (!attr_set) {
        cudaFuncSetAttribute(dgm_main, cudaFuncAttributeMaxDynamicSharedMemorySize, smem_bytes);
        attr_set = true;
    }

    prep_kernel<<<64, 256>>>(wzl, wgl, wrl, whl, uzl, ugl, url, uhl, w1);
    build_kernel<<<BTOT / 256, 256>>>(inputs, eps);
    dgm_main<<<NTILES, THREADS, smem_bytes>>>(w1, b1, uzl, wzl, bzl, ugl, wgl, bgl,
                                              url, wrl, brl, uhl, whl, bhl, w, b);
    epilogue_kernel<<<NPT / 8, 256>>>(out);
}

// round 12
// speedup vs baseline: 1.0004x; 1.0004x over previous
#include <cuda_runtime.h>
#include <math.h>

#define DIMX   20
#define DD     21
#define NPT    2048
#define MCc    32
#define UNITS  128
#define TP     16
#define BTOT   69632
#define NTILES (BTOT / TP)
#define THREADS 512

#define SIGc   0.2f
#define MUc    0.05f
#define Rc     0.05f
#define DELTAc 0.01f

__device__ float g_L[DIMX * DIMX];
__device__ float g_WT[4 * UNITS * UNITS];   // [mat][a][b] = W[b][a]
__device__ float g_UcatT[5 * UNITS * 24];   // [v][j][24] padded
__device__ float g_X[BTOT * DD];
__device__ float g_FP[BTOT * DD];
__device__ float g_FVAL[BTOT];

// smem (floats): matmul operands only; activations live in registers.
#define SM_X    0                    // 336
#define SM_S0   336                  // 2048
#define SM_S1   (SM_S0 + 2048)
#define SM_SR   (SM_S1 + 2048)
#define SM_T0   (SM_SR + 2048)       // staging daz / Daz
#define SM_T1   (SM_T0 + 2048)       // dag / Dag
#define SM_T2   (SM_T1 + 2048)       // dar / Dar
#define SM_T3   (SM_T2 + 2048)       // dah / Dah
#define SM_FRED (SM_T3 + 2048)       // 64
#define SM_TOT  (SM_FRED + 64)       // 14736 floats = 58944 B -> L1D ~169 KB

typedef unsigned long long u64t;

__device__ __forceinline__ u64t pack2(float lo, float hi) {
    u64t r;
    asm("mov.b64 %0, {%1, %2};" : "=l"(r) : "f"(lo), "f"(hi));
    return r;
}
__device__ __forceinline__ float2 unpack2(u64t v) {
    float2 f;
    asm("mov.b64 {%0, %1}, %2;" : "=f"(f.x), "=f"(f.y) : "l"(v));
    return f;
}
__device__ __forceinline__ u64t ffma2(u64t a, u64t b, u64t c) {
    u64t d;
    asm("fma.rn.f32x2 %0, %1, %2, %3;" : "=l"(d) : "l"(a), "l"(b), "l"(c));
    return d;
}
__device__ __forceinline__ float ftanh(float x) {
    float ax = fabsf(x);
    float t = __expf(-2.0f * ax);
    float r = __fdividef(1.0f - t, 1.0f + t);
    return copysignf(r, x);
}

__global__ void prep_kernel(const float* __restrict__ wz, const float* __restrict__ wg,
                            const float* __restrict__ wr, const float* __restrict__ wh,
                            const float* __restrict__ uz, const float* __restrict__ ug,
                            const float* __restrict__ ur, const float* __restrict__ uh,
                            const float* __restrict__ w1)
{
    int idx = blockIdx.x * blockDim.x + threadIdx.x;
    int stride = gridDim.x * blockDim.x;

    for (int t = idx; t < 4 * UNITS * UNITS; t += stride) {
        int mat = t >> 14;
        int r   = t & 16383;
        int a   = r >> 7;
        int b   = r & 127;
        const float* W = (mat == 0) ? wz : (mat == 1) ? wg : (mat == 2) ? wr : wh;
        g_WT[t] = W[b * UNITS + a];
    }
    for (int t = idx; t < 5 * UNITS * 24; t += stride) {
        int v = t / (UNITS * 24);
        int r = t % (UNITS * 24);
        int j = r / 24;
        int d = r % 24;
        const float* U = (v == 0) ? uz : (v == 1) ? ug : (v == 2) ? ur : (v == 3) ? uh : w1;
        g_UcatT[t] = (d < DD) ? U[d * UNITS + j] : 0.0f;
    }
    if (idx == 0) {
        double Ld[DIMX][DIMX];
        for (int i = 0; i < DIMX; i++) {
            for (int j2 = 0; j2 <= i; j2++) {
                double s = 0.01 * (0.5 + (i == j2 ? 0.5 : 0.0));
                for (int k = 0; k < j2; k++) s -= Ld[i][k] * Ld[j2][k];
                Ld[i][j2] = (i == j2) ? sqrt(s) : s / Ld[j2][j2];
            }
        }
        for (int i = 0; i < DIMX; i++)
            for (int j2 = 0; j2 < DIMX; j2++)
                g_L[i * DIMX + j2] = (j2 <= i) ? (float)Ld[i][j2] : 0.0f;
    }
}

__global__ void build_kernel(const float* __restrict__ inputs, const float* __restrict__ eps)
{
    int r = blockIdx.x * blockDim.x + threadIdx.x;
    if (r >= BTOT) return;
    if (r < 4096) {
        #pragma unroll
        for (int d = 0; d < DD; d++) g_X[r * DD + d] = inputs[r * DD + d];
    } else {
        int q = r - 4096;
        int m = q >> 11;
        int n = q & 2047;
        float xr[DD];
        #pragma unroll
        for (int d = 0; d < DD; d++) xr[d] = inputs[n * DD + d];
        float e[DIMX];
        #pragma unroll
        for (int d = 0; d < DIMX; d++) e[d] = eps[(m * NPT + n) * DIMX + d];
        #pragma unroll
        for (int k = 0; k < DIMX; k++) {
            float acc = 0.f;
            #pragma unroll
            for (int d = 0; d < DIMX; d++) acc += e[d] * g_L[k * DIMX + d];
            float sample = xr[k] + acc;
            float viol = sample * (SIGc * xr[k]);
            g_X[r * DD + k] = xr[k] + viol;
        }
        g_X[r * DD + DIMX] = xr[DIMX];
    }
}

// ---- helpers ----
__device__ __forceinline__ void st4(float* dst, const float a[4], int j, int p0) {
    *(float4*)&dst[j * TP + p0] = make_float4(a[0], a[1], a[2], a[3]);
}
// single-matrix pass: a0/a1 += S_pairs * {w,w}   (5 issues per k)
__device__ __forceinline__ void mm1(u64t& a0, u64t& a1, const float* __restrict__ W,
                                    const float* S, int j, int p0) {
    #pragma unroll 8
    for (int k = 0; k < UNITS; k++) {
        float wv = W[k * UNITS + j];
        u64t wp = pack2(wv, wv);
        ulonglong2 s = *(const ulonglong2*)&S[k * TP + p0];
        a0 = ffma2(s.x, wp, a0);
        a1 = ffma2(s.y, wp, a1);
    }
}
// x@U (21 iterations, scalar)
__device__ __forceinline__ void mmX(float acc[4], const float* __restrict__ U,
                                    const float* X, int j, int p0) {
    #pragma unroll
    for (int d = 0; d < DD; d++) {
        float wv = U[d * UNITS + j];
        float4 s = *(const float4*)&X[d * TP + p0];
        acc[0] += s.x * wv; acc[1] += s.y * wv; acc[2] += s.z * wv; acc[3] += s.w * wv;
    }
}
__device__ __forceinline__ void tanh4(float out[4], u64t a0, u64t a1) {
    float2 t0 = unpack2(a0), t1 = unpack2(a1);
    out[0] = ftanh(t0.x); out[1] = ftanh(t0.y); out[2] = ftanh(t1.x); out[3] = ftanh(t1.y);
}

__global__ __launch_bounds__(THREADS, 1)
void dgm_main(const float* __restrict__ w1, const float* __restrict__ b1,
              const float* __restrict__ uz, const float* __restrict__ wz, const float* __restrict__ bz,
              const float* __restrict__ ug, const float* __restrict__ wg, const float* __restrict__ bg,
              const float* __restrict__ ur, const float* __restrict__ wr, const float* __restrict__ br,
              const float* __restrict__ uh, const float* __restrict__ wh, const float* __restrict__ bh,
              const float* __restrict__ wout, const float* __restrict__ bout)
{
    extern __shared__ float sm[];
    const int tid = threadIdx.x;
    const int j   = tid & 127;
    const int pg  = tid >> 7;
    const int p0  = pg * 4;
    const int base = blockIdx.x * TP;
    const bool doGrad = !(blockIdx.x >= 128 && blockIdx.x < 256);

    for (int t = tid; t < TP * DD; t += THREADS) {
        int p = t / DD, d = t % DD;
        sm[SM_X + d * TP + p] = g_X[(base + p) * DD + d];
    }
    __syncthreads();

    // ---- prologue: x@U + b (kept as f32x2 pairs across the layers) ----
    u64t xzr[2], xgr[2], xrr[2], xhr[2];
    float s_cur[4];
    float slr[3][4];                     // s input of each layer (registers)
    {
        float acc[4];
        float bb;
        bb = bz[j];
        acc[0]=acc[1]=acc[2]=acc[3]=bb; mmX(acc, uz, &sm[SM_X], j, p0);
        xzr[0] = pack2(acc[0], acc[1]); xzr[1] = pack2(acc[2], acc[3]);
        bb = bg[j];
        acc[0]=acc[1]=acc[2]=acc[3]=bb; mmX(acc, ug, &sm[SM_X], j, p0);
        xgr[0] = pack2(acc[0], acc[1]); xgr[1] = pack2(acc[2], acc[3]);
        bb = br[j];
        acc[0]=acc[1]=acc[2]=acc[3]=bb; mmX(acc, ur, &sm[SM_X], j, p0);
        xrr[0] = pack2(acc[0], acc[1]); xrr[1] = pack2(acc[2], acc[3]);
        bb = bh[j];
        acc[0]=acc[1]=acc[2]=acc[3]=bb; mmX(acc, uh, &sm[SM_X], j, p0);
        xhr[0] = pack2(acc[0], acc[1]); xhr[1] = pack2(acc[2], acc[3]);
        bb = b1[j];
        acc[0]=acc[1]=acc[2]=acc[3]=bb; mmX(acc, w1, &sm[SM_X], j, p0);
        #pragma unroll
        for (int p = 0; p < 4; p++) s_cur[p] = ftanh(acc[p]);
        st4(&sm[SM_S0], s_cur, j, p0);
    }
    __syncthreads();

    // ---- forward: activations retained in registers for backward ----
    float zr[3][4], gr[3][4], rr[3][4], hr[3][4];
    #pragma unroll 1
    for (int l = 0; l < 3; l++) {
        float* Sin = (l & 1) ? &sm[SM_S1] : &sm[SM_S0];
        float* Sout = (l & 1) ? &sm[SM_S0] : &sm[SM_S1];
        #pragma unroll
        for (int p = 0; p < 4; p++) slr[l][p] = s_cur[p];

        // z / g / r: three single-matrix passes (each 64 KB, L1-resident)
        u64t a0, a1;
        a0 = xzr[0]; a1 = xzr[1];
        mm1(a0, a1, wz, Sin, j, p0);
        tanh4(zr[l], a0, a1);
        a0 = xgr[0]; a1 = xgr[1];
        mm1(a0, a1, wg, Sin, j, p0);
        tanh4(gr[l], a0, a1);
        a0 = xrr[0]; a1 = xrr[1];
        mm1(a0, a1, wr, Sin, j, p0);
        tanh4(rr[l], a0, a1);

        float sr4[4];
        #pragma unroll
        for (int p = 0; p < 4; p++) sr4[p] = s_cur[p] * rr[l][p];
        st4(&sm[SM_SR], sr4, j, p0);
        __syncthreads();

        a0 = xhr[0]; a1 = xhr[1];
        mm1(a0, a1, wh, &sm[SM_SR], j, p0);
        tanh4(hr[l], a0, a1);

        #pragma unroll
        for (int p = 0; p < 4; p++)
            s_cur[p] = (1.0f - gr[l][p]) * hr[l][p] + zr[l][p] * s_cur[p];
        if (l < 2) st4(Sout, s_cur, j, p0);
        __syncthreads();
    }

    // ---- value f = s3@w + b ----
    {
        float wv = wout[j];
        int warpId = tid >> 5;
        #pragma unroll
        for (int p = 0; p < 4; p++) {
            float v = wv * s_cur[p];
            #pragma unroll
            for (int off = 16; off; off >>= 1) v += __shfl_xor_sync(0xffffffffu, v, off);
            if ((tid & 31) == 0) sm[SM_FRED + warpId * 4 + p] = v;
        }
        __syncthreads();
        if (tid < TP) {
            int p = tid;
            int pgp = p >> 2;
            float f = bout[0];
            #pragma unroll
            for (int q = 0; q < 4; q++) f += sm[SM_FRED + (pgp * 4 + q) * 4 + (p & 3)];
            g_FVAL[base + p] = f;
        }
    }

    if (!doGrad) return;

    // ---- backward ----
    float ds[4], Daz[4], Dag[4], Dar[4], Dah[4];
    {
        float wv = wout[j];
        #pragma unroll
        for (int p = 0; p < 4; p++) {
            ds[p] = wv;
            Daz[p] = 0.f; Dag[p] = 0.f; Dar[p] = 0.f; Dah[p] = 0.f;
        }
    }

    #pragma unroll 1
    for (int l = 2; l >= 0; l--) {
        // stage A: elementwise from registers; stage daz/dag/dah to smem
        {
            float daz[4], dag[4], dah[4];
            #pragma unroll
            for (int p = 0; p < 4; p++) {
                float z = zr[l][p], g = gr[l][p], h = hr[l][p], sl = slr[l][p];
                float dsp = ds[p];
                float dh = dsp * (1.0f - g);
                float dg = -dsp * h;
                float dz = dsp * sl;
                daz[p] = dz * (1.0f - z * z);
                dag[p] = dg * (1.0f - g * g);
                dah[p] = dh * (1.0f - h * h);
                Daz[p] += daz[p]; Dag[p] += dag[p]; Dah[p] += dah[p];
                ds[p] = dsp * z;
            }
            st4(&sm[SM_T0], daz, j, p0);
            st4(&sm[SM_T1], dag, j, p0);
            st4(&sm[SM_T3], dah, j, p0);
        }
        __syncthreads();

        // stage B: dsr = dah @ Wh^T (single-matrix pass)
        float dsr[4];
        {
            u64t b0 = pack2(0.f, 0.f), b1p = pack2(0.f, 0.f);
            mm1(b0, b1p, g_WT + 3 * UNITS * UNITS, &sm[SM_T3], j, p0);
            float2 t0 = unpack2(b0), t1 = unpack2(b1p);
            dsr[0] = t0.x; dsr[1] = t0.y; dsr[2] = t1.x; dsr[3] = t1.y;
        }

        // stage C: dar from registers; stage to smem
        {
            float dar[4];
            #pragma unroll
            for (int p = 0; p < 4; p++) {
                float r = rr[l][p], sl = slr[l][p];
                ds[p] += dsr[p] * r;
                dar[p] = (dsr[p] * sl) * (1.0f - r * r);
                Dar[p] += dar[p];
            }
            st4(&sm[SM_T2], dar, j, p0);
        }
        __syncthreads();

        // stage D: three single-matrix passes
        {
            u64t d0 = pack2(ds[0], ds[1]), d1 = pack2(ds[2], ds[3]);
            mm1(d0, d1, g_WT + 0 * UNITS * UNITS, &sm[SM_T0], j, p0);
            mm1(d0, d1, g_WT + 1 * UNITS * UNITS, &sm[SM_T1], j, p0);
            mm1(d0, d1, g_WT + 2 * UNITS * UNITS, &sm[SM_T2], j, p0);
            float2 t0 = unpack2(d0), t1 = unpack2(d1);
            ds[0] = t0.x; ds[1] = t0.y; ds[2] = t1.x; ds[3] = t1.y;
        }
        __syncthreads();   // WAR: next stage A rewrites staging arrays
    }

    // write Σda accumulators + da1 for the dx product
    {
        float da1[4];
        #pragma unroll
        for (int p = 0; p < 4; p++) {
            float s0 = slr[0][p];
            da1[p] = ds[p] * (1.0f - s0 * s0);
        }
        st4(&sm[SM_T0], Daz, j, p0);
        st4(&sm[SM_T1], Dag, j, p0);
        st4(&sm[SM_T2], Dar, j, p0);
        st4(&sm[SM_T3], Dah, j, p0);
        st4(&sm[SM_SR], da1, j, p0);
    }
    __syncthreads();

    // dx stage 1: partials over (p, d-quad, v) -> scratch in S0 buffer
    if (tid < 480) {
        int v  = tid % 5;
        int dq = (tid / 5) % 6;
        int p  = tid / 30;
        int d0 = dq * 4;
        const float* slot =
            (v == 0) ? &sm[SM_T0] : (v == 1) ? &sm[SM_T1] :
            (v == 2) ? &sm[SM_T2] : (v == 3) ? &sm[SM_T3] : &sm[SM_SR];
        const float* Ut = g_UcatT + v * UNITS * 24;
        float acc[4] = {0.f, 0.f, 0.f, 0.f};
        #pragma unroll 8
        for (int k = 0; k < UNITS; k++) {
            float a = slot[k * TP + p];
            float4 u = *(const float4*)&Ut[k * 24 + d0];
            acc[0] += a * u.x; acc[1] += a * u.y; acc[2] += a * u.z; acc[3] += a * u.w;
        }
        *(float4*)&sm[SM_S0 + ((p * 6 + dq) * 5 + v) * 4] = make_float4(acc[0], acc[1], acc[2], acc[3]);
    }
    __syncthreads();

    // dx stage 2: combine 5 partials, coalesced-ish write
    if (tid < 96) {
        int p  = tid / 6;
        int dq = tid % 6;
        int d0 = dq * 4;
        float acc[4] = {0.f, 0.f, 0.f, 0.f};
        #pragma unroll
        for (int v = 0; v < 5; v++) {
            float4 t = *(const float4*)&sm[SM_S0 + ((p * 6 + dq) * 5 + v) * 4];
            acc[0] += t.x; acc[1] += t.y; acc[2] += t.z; acc[3] += t.w;
        }
        #pragma unroll
        for (int i = 0; i < 4; i++) {
            int d = d0 + i;
            if (d < DD) g_FP[(base + p) * DD + d] = acc[i];
        }
    }
}

__global__ void epilogue_kernel(float* __restrict__ out)
{
    int warpId = threadIdx.x >> 5;
    int lane   = threadIdx.x & 31;
    int n = blockIdx.x * 8 + warpId;
    if (n >= NPT) return;

    const float* fp1 = &g_FP[n * DD];
    const float* x1r = &g_X[n * DD];
    int rp = (4096 + lane * NPT + n) * DD;
    const float* fpp = &g_FP[rp];
    const float* xp  = &g_X[rp];

    float part = 0.f;
    #pragma unroll
    for (int k = 0; k < DIMX; k++) {
        float viol = xp[k] - x1r[k];
        part += (fpp[k] - fp1[k]) * viol;
    }
    #pragma unroll
    for (int off = 16; off; off >>= 1) part += __shfl_xor_sync(0xffffffffu, part, off);

    if (lane == 0) {
        float term12 = part / (DELTAc * (float)MCc);
        float term11 = fp1[DIMX];
        #pragma unroll
        for (int k = 0; k < DIMX; k++) term11 += MUc * x1r[k] * fp1[k];
        out[n] = term11 + 0.5f * term12 - Rc * g_FVAL[n];

        const float* x2r = &g_X[(NPT + n) * DD];
        float prod = 1.f;
        #pragma unroll
        for (int k = 0; k < DIMX; k++) prod *= x2r[k];
        float payoff = powf(prod, 1.0f / (float)DIMX);
        payoff = fmaxf(payoff, 0.f);
        out[NPT + n] = g_FVAL[NPT + n] - payoff;
    }
}

extern "C" void kernel_launch(void* const* d_in, const int* in_sizes, int n_in,
                              void* d_out, int out_size)
{
    (void)in_sizes; (void)n_in; (void)out_size;
    const float* inputs = (const float*)d_in[0];
    const float* eps    = (const float*)d_in[1];
    const float* w1  = (const float*)d_in[2];
    const float* b1  = (const float*)d_in[3];
    const float* uzl = (const float*)d_in[4];
    const float* wzl = (const float*)d_in[5];
    const float* bzl = (const float*)d_in[6];
    const float* ugl = (const float*)d_in[7];
    const float* wgl = (const float*)d_in[8];
    const float* bgl = (const float*)d_in[9];
    const float* url = (const float*)d_in[10];
    const float* wrl = (const float*)d_in[11];
    const float* brl = (const float*)d_in[12];
    const float* uhl = (const float*)d_in[13];
    const float* whl = (const float*)d_in[14];
    const float* bhl = (const float*)d_in[15];
    const float* w   = (const float*)d_in[16];
    const float* b   = (const float*)d_in[17];
    float* out = (float*)d_out;

    const int smem_bytes = SM_TOT * (int)sizeof(float);
    static bool attr_set = false;
    if (!attr_set) {
        cudaFuncSetAttribute(dgm_main, cudaFuncAttributeMaxDynamicSharedMemorySize, smem_bytes);
        attr_set = true;
    }

    prep_kernel<<<64, 256>>>(wzl, wgl, wrl, whl, uzl, ugl, url, uhl, w1);
    build_kernel<<<BTOT / 256, 256>>>(inputs, eps);
    dgm_main<<<NTILES, THREADS, smem_bytes>>>(w1, b1, uzl, wzl, bzl, ugl, wgl, bgl,
                                              url, wrl, brl, uhl, whl, bhl, w, b);
    epilogue_kernel<<<NPT / 8, 256>>>(out);
}